// round 1
// baseline (speedup 1.0000x reference)
#include <cuda_runtime.h>

#define BATCH 2
#define SEQ   2048
#define DM    1024
#define NH    16
#define HD    64

// Scratch (allocation-free rule: __device__ globals)
__device__ float g_Q[(size_t)BATCH * NH * SEQ * HD];
__device__ float g_K[(size_t)BATCH * NH * SEQ * HD];
__device__ float g_V[(size_t)BATCH * NH * SEQ * HD];
__device__ float g_C[(size_t)BATCH * SEQ * DM];

// ---------------------------------------------------------------------------
// Kernel 1: per-head QKV projection.
// out[b,h,s,e] = sum_d x[b,s,d] * W[h,d,e] + bias[h,e]
// Grid: (SEQ/64, BATCH*NH). Block: 256 threads (16x16), 4x4 micro-tile.
// sel: 0 -> g_Q, 1 -> g_K, 2 -> g_V
// ---------------------------------------------------------------------------
__global__ __launch_bounds__(256)
void qkv_proj_kernel(const float* __restrict__ x, const float* __restrict__ W,
                     const float* __restrict__ bias, int sel)
{
    __shared__ float As[16][68];   // [k][m], padded
    __shared__ float Bs[16][68];   // [k][e], padded

    const int tid = threadIdx.x;
    const int tx = tid & 15, ty = tid >> 4;
    const int bh = blockIdx.y;
    const int h  = bh & (NH - 1);
    const int b  = bh >> 4;
    const int s0 = blockIdx.x * 64;

    const float* A  = x + (size_t)b * SEQ * DM;            // [SEQ][DM]
    const float* Bw = W + (size_t)h * DM * HD;             // [DM][HD]
    float* out = (sel == 0) ? g_Q : (sel == 1) ? g_K : g_V;

    const int am  = tid >> 2;           // 0..63   A loader row
    const int akq = (tid & 3) * 4;      // 0,4,8,12 A loader k-quad
    const int bk  = tid >> 4;           // 0..15   B loader k
    const int beq = (tid & 15) * 4;     // B loader e-quad

    float acc[4][4] = {};

    for (int k0 = 0; k0 < DM; k0 += 16) {
        float4 a4 = *(const float4*)(A + (size_t)(s0 + am) * DM + k0 + akq);
        As[akq + 0][am] = a4.x; As[akq + 1][am] = a4.y;
        As[akq + 2][am] = a4.z; As[akq + 3][am] = a4.w;
        float4 b4 = *(const float4*)(Bw + (size_t)(k0 + bk) * HD + beq);
        *(float4*)&Bs[bk][beq] = b4;
        __syncthreads();

        #pragma unroll
        for (int k = 0; k < 16; k++) {
            float4 av = *(float4*)&As[k][ty * 4];
            float4 bv = *(float4*)&Bs[k][tx * 4];
            float a[4] = {av.x, av.y, av.z, av.w};
            float bb[4] = {bv.x, bv.y, bv.z, bv.w};
            #pragma unroll
            for (int i = 0; i < 4; i++)
                #pragma unroll
                for (int j = 0; j < 4; j++)
                    acc[i][j] = fmaf(a[i], bb[j], acc[i][j]);
        }
        __syncthreads();
    }

    float4 bb4 = *(const float4*)(bias + h * HD + tx * 4);
    #pragma unroll
    for (int i = 0; i < 4; i++) {
        float4 o;
        o.x = acc[i][0] + bb4.x; o.y = acc[i][1] + bb4.y;
        o.z = acc[i][2] + bb4.z; o.w = acc[i][3] + bb4.w;
        *(float4*)(out + ((size_t)bh * SEQ + s0 + ty * 4 + i) * HD + tx * 4) = o;
    }
}

// ---------------------------------------------------------------------------
// Kernel 2: flash attention per (b,h), BM=64 query rows per block, key tiles
// of 64, online softmax. Writes concat layout g_C[b, s, h*HD + e].
// Grid: (SEQ/64, BATCH*NH). Block 256 (16x16), 4x4 micro-tile.
// Dynamic shared memory.
// ---------------------------------------------------------------------------
#define ATTN_SMEM_FLOATS (4 * 64 * 68 + 64 * 17 + 3 * 64)
#define ATTN_SMEM_BYTES  (ATTN_SMEM_FLOATS * 4)

__global__ __launch_bounds__(256)
void attn_kernel()
{
    extern __shared__ float sm[];
    float (*Qs)[68]  = (float(*)[68])(sm);                 // [e][m]
    float (*Ks)[68]  = (float(*)[68])(sm + 1 * 64 * 68);   // [e][c]
    float (*Vs)[68]  = (float(*)[68])(sm + 2 * 64 * 68);   // [c][e]
    float (*Ps)[68]  = (float(*)[68])(sm + 3 * 64 * 68);   // [c][r] (P transposed)
    float (*red)[17] = (float(*)[17])(sm + 4 * 64 * 68);   // [row][tx]
    float* m_s  = sm + 4 * 64 * 68 + 64 * 17;
    float* l_s  = m_s + 64;
    float* al_s = l_s + 64;

    const int tid = threadIdx.x;
    const int tx = tid & 15, ty = tid >> 4;
    const int bh = blockIdx.y;
    const int h  = bh & (NH - 1);
    const int b  = bh >> 4;
    const int s0 = blockIdx.x * 64;

    const float* Qg = g_Q + (size_t)bh * SEQ * HD;
    const float* Kg = g_K + (size_t)bh * SEQ * HD;
    const float* Vg = g_V + (size_t)bh * SEQ * HD;

    const int lm  = tid >> 4;           // 0..15 loader row base
    const int leq = (tid & 15) * 4;     // e-quad

    // Load Q tile transposed: Qs[e][m]
    #pragma unroll
    for (int mo = 0; mo < 64; mo += 16) {
        float4 q = *(const float4*)(Qg + (size_t)(s0 + lm + mo) * HD + leq);
        Qs[leq + 0][lm + mo] = q.x; Qs[leq + 1][lm + mo] = q.y;
        Qs[leq + 2][lm + mo] = q.z; Qs[leq + 3][lm + mo] = q.w;
    }
    if (tid < 64) { m_s[tid] = -1e30f; l_s[tid] = 0.0f; }

    float O[4][4] = {};

    for (int c0 = 0; c0 < SEQ; c0 += 64) {
        // Load K transposed (Ks[e][c]) and V straight (Vs[c][e])
        #pragma unroll
        for (int mo = 0; mo < 64; mo += 16) {
            float4 kv = *(const float4*)(Kg + (size_t)(c0 + lm + mo) * HD + leq);
            Ks[leq + 0][lm + mo] = kv.x; Ks[leq + 1][lm + mo] = kv.y;
            Ks[leq + 2][lm + mo] = kv.z; Ks[leq + 3][lm + mo] = kv.w;
            float4 vv = *(const float4*)(Vg + (size_t)(c0 + lm + mo) * HD + leq);
            *(float4*)&Vs[lm + mo][leq] = vv;
        }
        __syncthreads();

        // S = Q * K^T  (rows r = ty*4+i, cols c = tx*4+j)
        float s[4][4] = {};
        #pragma unroll 8
        for (int e = 0; e < 64; e++) {
            float4 av = *(float4*)&Qs[e][ty * 4];
            float4 bv = *(float4*)&Ks[e][tx * 4];
            float a[4] = {av.x, av.y, av.z, av.w};
            float bb[4] = {bv.x, bv.y, bv.z, bv.w};
            #pragma unroll
            for (int i = 0; i < 4; i++)
                #pragma unroll
                for (int j = 0; j < 4; j++)
                    s[i][j] = fmaf(a[i], bb[j], s[i][j]);
        }

        // scale + per-thread row max
        #pragma unroll
        for (int i = 0; i < 4; i++) {
            float rm = -1e30f;
            #pragma unroll
            for (int j = 0; j < 4; j++) {
                s[i][j] *= 0.125f;   // 1/sqrt(64)
                rm = fmaxf(rm, s[i][j]);
            }
            red[ty * 4 + i][tx] = rm;
        }
        __syncthreads();

        // row leaders: new max, alpha, rescale l
        if (tid < 64) {
            float t = red[tid][0];
            #pragma unroll
            for (int k = 1; k < 16; k++) t = fmaxf(t, red[tid][k]);
            float mo_ = m_s[tid];
            float mn  = fmaxf(mo_, t);
            float al  = __expf(mo_ - mn);
            m_s[tid]  = mn;
            al_s[tid] = al;
            l_s[tid] *= al;
        }
        __syncthreads();

        // p = exp(s - m), write P^T, accumulate row sums, rescale O
        #pragma unroll
        for (int i = 0; i < 4; i++) {
            const int r = ty * 4 + i;
            const float mr = m_s[r];
            const float a  = al_s[r];
            float rsum = 0.0f;
            #pragma unroll
            for (int j = 0; j < 4; j++) {
                float p = __expf(s[i][j] - mr);
                Ps[tx * 4 + j][r] = p;
                rsum += p;
            }
            #pragma unroll
            for (int j = 0; j < 4; j++) O[i][j] *= a;
            red[r][tx] = rsum;
        }
        __syncthreads();

        if (tid < 64) {
            float t = 0.0f;
            #pragma unroll
            for (int k = 0; k < 16; k++) t += red[tid][k];
            l_s[tid] += t;
        }

        // O += P * V  (rows r = ty*4+i, cols e = tx*4+j)
        #pragma unroll 8
        for (int c = 0; c < 64; c++) {
            float4 av = *(float4*)&Ps[c][ty * 4];
            float4 bv = *(float4*)&Vs[c][tx * 4];
            float a[4] = {av.x, av.y, av.z, av.w};
            float bb[4] = {bv.x, bv.y, bv.z, bv.w};
            #pragma unroll
            for (int i = 0; i < 4; i++)
                #pragma unroll
                for (int j = 0; j < 4; j++)
                    O[i][j] = fmaf(a[i], bb[j], O[i][j]);
        }
        __syncthreads();
    }

    // Normalize and store concat layout [B, S, H*HD]
    #pragma unroll
    for (int i = 0; i < 4; i++) {
        const int r = ty * 4 + i;
        const float inv = 1.0f / l_s[r];
        float4 o;
        o.x = O[i][0] * inv; o.y = O[i][1] * inv;
        o.z = O[i][2] * inv; o.w = O[i][3] * inv;
        *(float4*)(g_C + ((size_t)b * SEQ + s0 + r) * DM + h * HD + tx * 4) = o;
    }
}

// ---------------------------------------------------------------------------
// Kernel 3: output projection: out[m,n] = sum_k C[m,k] * Wp[n,k] + bp[n]
// M = BATCH*SEQ = 4096, N = K = 1024. Grid: (N/64, M/64). Block 256.
// ---------------------------------------------------------------------------
__global__ __launch_bounds__(256)
void out_proj_kernel(const float* __restrict__ Wp, const float* __restrict__ bp,
                     float* __restrict__ out)
{
    __shared__ float As[16][68];   // [k][m]
    __shared__ float Bs[16][68];   // [k][n]

    const int tid = threadIdx.x;
    const int tx = tid & 15, ty = tid >> 4;
    const int n0 = blockIdx.x * 64;
    const int m0 = blockIdx.y * 64;

    const int am  = tid >> 2;       // 0..63 (row for A, n for B)
    const int akq = (tid & 3) * 4;  // k-quad

    float acc[4][4] = {};

    for (int k0 = 0; k0 < DM; k0 += 16) {
        float4 a4 = *(const float4*)(g_C + (size_t)(m0 + am) * DM + k0 + akq);
        As[akq + 0][am] = a4.x; As[akq + 1][am] = a4.y;
        As[akq + 2][am] = a4.z; As[akq + 3][am] = a4.w;
        float4 w4 = *(const float4*)(Wp + (size_t)(n0 + am) * DM + k0 + akq);
        Bs[akq + 0][am] = w4.x; Bs[akq + 1][am] = w4.y;
        Bs[akq + 2][am] = w4.z; Bs[akq + 3][am] = w4.w;
        __syncthreads();

        #pragma unroll
        for (int k = 0; k < 16; k++) {
            float4 av = *(float4*)&As[k][ty * 4];
            float4 bv = *(float4*)&Bs[k][tx * 4];
            float a[4] = {av.x, av.y, av.z, av.w};
            float bb[4] = {bv.x, bv.y, bv.z, bv.w};
            #pragma unroll
            for (int i = 0; i < 4; i++)
                #pragma unroll
                for (int j = 0; j < 4; j++)
                    acc[i][j] = fmaf(a[i], bb[j], acc[i][j]);
        }
        __syncthreads();
    }

    float4 bb4 = *(const float4*)(bp + n0 + tx * 4);
    #pragma unroll
    for (int i = 0; i < 4; i++) {
        float4 o;
        o.x = acc[i][0] + bb4.x; o.y = acc[i][1] + bb4.y;
        o.z = acc[i][2] + bb4.z; o.w = acc[i][3] + bb4.w;
        *(float4*)(out + (size_t)(m0 + ty * 4 + i) * DM + n0 + tx * 4) = o;
    }
}

// ---------------------------------------------------------------------------
extern "C" void kernel_launch(void* const* d_in, const int* in_sizes, int n_in,
                              void* d_out, int out_size)
{
    (void)in_sizes; (void)n_in; (void)out_size;
    const float* x  = (const float*)d_in[0];
    const float* Wq = (const float*)d_in[1];
    const float* Wk = (const float*)d_in[2];
    const float* Wv = (const float*)d_in[3];
    const float* bq = (const float*)d_in[4];
    const float* bk = (const float*)d_in[5];
    const float* bv = (const float*)d_in[6];
    const float* Wp = (const float*)d_in[7];
    const float* bp = (const float*)d_in[8];
    float* out = (float*)d_out;

    dim3 blk(256);

    // QKV projections
    dim3 g1(SEQ / 64, BATCH * NH);
    qkv_proj_kernel<<<g1, blk>>>(x, Wq, bq, 0);
    qkv_proj_kernel<<<g1, blk>>>(x, Wk, bk, 1);
    qkv_proj_kernel<<<g1, blk>>>(x, Wv, bv, 2);

    // Flash attention
    cudaFuncSetAttribute(attn_kernel,
                         cudaFuncAttributeMaxDynamicSharedMemorySize,
                         ATTN_SMEM_BYTES);
    dim3 g2(SEQ / 64, BATCH * NH);
    attn_kernel<<<g2, blk, ATTN_SMEM_BYTES>>>();

    // Output projection
    dim3 g3(DM / 64, (BATCH * SEQ) / 64);
    out_proj_kernel<<<g3, blk>>>(Wp, bp, out);
}